// round 12
// baseline (speedup 1.0000x reference)
#include <cuda_runtime.h>
#include <cstdint>

#define BB 8
#define CC 128
#define NN 4096
#define KK 8
#define TM 128
#define TN 64

// ---- device scratch (no allocations allowed) ----
__device__ float g_xx[BB * NN];
__device__ int   g_idx[BB * NN * KK];
__device__ float g_G[(size_t)BB * CC * NN];
__device__ float g_WT[CC * CC];
__device__ float g_PT[(size_t)BB * NN * CC];   // points transposed: [b][n][c]

__device__ __forceinline__ float lrelu(float x) { return x > 0.f ? x : 0.01f * x; }

extern __shared__ __align__(16) float smem[];

// ---------------- xx[b,n] = sum_c points^2 ----------------
__global__ void xx_kernel(const float* __restrict__ pts) {
    int t = blockIdx.x * blockDim.x + threadIdx.x;   // b*N + n
    int b = t >> 12, n = t & (NN - 1);
    const float* p = pts + (size_t)b * CC * NN + n;
    float s = 0.f;
#pragma unroll
    for (int c = 0; c < CC; c++) { float v = p[(size_t)c * NN]; s = fmaf(v, v, s); }
    g_xx[t] = s;
}

// ---------------- transpose conv2_w -> g_WT[c][o] ----------------
__global__ void wt_kernel(const float* __restrict__ w) {
    int t = blockIdx.x * blockDim.x + threadIdx.x;   // o*128 + c
    int o = t >> 7, c = t & 127;
    g_WT[c * CC + o] = w[t];
}

// ---------------- transpose points -> g_PT[b][n][c] ----------------
__global__ void pt_kernel(const float* __restrict__ pts) {
    __shared__ float t[32][33];
    int b  = blockIdx.z;
    int c0 = blockIdx.y * 32, n0 = blockIdx.x * 32;
    for (int i = threadIdx.y; i < 32; i += 8)
        t[i][threadIdx.x] = pts[(size_t)b * CC * NN + (size_t)(c0 + i) * NN + n0 + threadIdx.x];
    __syncthreads();
    for (int i = threadIdx.y; i < 32; i += 8)
        g_PT[((size_t)b * NN + n0 + i) * CC + c0 + threadIdx.x] = t[threadIdx.x][i];
}

// ---------------- fused Gram + top-8 (the hot kernel) ----------------
// 128 threads/CTA, 2 CTAs/SM. Thread = 8 rows (rg*4+{0..3} and 64+rg*4+{0..3})
// x 8 cols (cg*8..cg*8+7). A loaded as 2 conflict-free ld.shared.v2.b64 giving
// NATURAL row-pairs for FFMA2 (no A packs); B via 2 broadcast ld.shared.v4.b32
// + 8 dup packs. Per-(row,col) accumulation chain over k and the score
// expression 2*inner - xr - xc are bit-identical to the verified round-6
// kernel, so fp32 selection decisions match the reference's top_k everywhere.
#define FMA2(ACC, A, Bv) asm("fma.rn.f32x2 %0,%1,%2,%0;" : "+l"(ACC) : "l"(A), "l"(Bv))

#define SMEM_FLOATS (CC * TM + CC * TN + 32 * 128)   // 28672 floats = 112KB

__global__ void __launch_bounds__(128, 2) gram_topk_kernel(const float* __restrict__ pts) {
    float* As = smem;                 // [k][r] 128x128 = 64KB
    float* Bs = As + CC * TM;         // [k][c] 128x64  = 32KB
    float* Ss = Bs + CC * TN;         // [32][128] col-major chunk = 16KB

    const int tid  = threadIdx.x;
    const int rg   = tid & 15;        // row group
    const int cg   = tid >> 4;        // col group (0..7)
    const int ra   = rg * 4;          // rows ra..ra+3
    const int rb   = 64 + rg * 4;     // rows rb..rb+3
    const int c0   = cg * 8;          // cols c0..c0+7
    const int chunkq  = cg >> 2;      // which 32-col chunk this thread stages
    const int clcBase = (cg & 3) * 8; // col offset within chunk

    const int b    = blockIdx.y;
    const int row0 = blockIdx.x * TM;
    const float* P = pts + (size_t)b * CC * NN;

    // Load A tile once (coalesced, k-major, rows contiguous)
    for (int i = tid; i < CC * TM / 4; i += 128) {
        int k = i >> 5, r4 = (i & 31) << 2;
        *(float4*)(As + k * TM + r4) = *(const float4*)(P + (size_t)k * NN + row0 + r4);
    }

    // row norms for this thread's 8 rows
    float4 xra = *(const float4*)(g_xx + b * NN + row0 + ra);
    float4 xrb = *(const float4*)(g_xx + b * NN + row0 + rb);

    // per-thread sorted top-8 (thread owns row row0+tid for the scan)
    float sc[KK]; int ix[KK];
#pragma unroll
    for (int p = 0; p < KK; p++) { sc[p] = -3e38f; ix[p] = 0; }

    unsigned aAddr = (unsigned)__cvta_generic_to_shared(As) + rg * 16;
    unsigned bAddr = (unsigned)__cvta_generic_to_shared(Bs) + cg * 32;

    for (int ct = 0; ct < NN / TN; ct++) {
        const int col0 = ct * TN;

        for (int i = tid; i < CC * TN / 4; i += 128) {
            int k = i >> 4, c4 = (i & 15) << 2;
            *(float4*)(Bs + k * TN + c4) = *(const float4*)(P + (size_t)k * NN + col0 + c4);
        }
        __syncthreads();

        // col norms for this thread's 8 cols (hidden under compute)
        float4 xq0 = *(const float4*)(g_xx + b * NN + col0 + c0);
        float4 xq1 = *(const float4*)(g_xx + b * NN + col0 + c0 + 4);

        unsigned long long acc[32];   // acc[p*8+j]: row-pair p, col c0+j
#pragma unroll
        for (int i = 0; i < 32; i++) acc[i] = 0ULL;

#pragma unroll 4
        for (int k = 0; k < CC; k++) {
            unsigned long long A0, A1, A2, A3;
            asm volatile("ld.shared.v2.b64 {%0,%1},[%2];"
                         : "=l"(A0), "=l"(A1) : "r"(aAddr + k * (TM * 4)));
            asm volatile("ld.shared.v2.b64 {%0,%1},[%2];"
                         : "=l"(A2), "=l"(A3) : "r"(aAddr + k * (TM * 4) + 256));
            float b0, b1, b2, b3, b4, b5, b6, b7;
            asm volatile("ld.shared.v4.b32 {%0,%1,%2,%3},[%4];"
                         : "=f"(b0), "=f"(b1), "=f"(b2), "=f"(b3)
                         : "r"(bAddr + k * (TN * 4)));
            asm volatile("ld.shared.v4.b32 {%0,%1,%2,%3},[%4];"
                         : "=f"(b4), "=f"(b5), "=f"(b6), "=f"(b7)
                         : "r"(bAddr + k * (TN * 4) + 16));
            unsigned long long Bd[8];
            asm("mov.b64 %0,{%1,%1};" : "=l"(Bd[0]) : "f"(b0));
            asm("mov.b64 %0,{%1,%1};" : "=l"(Bd[1]) : "f"(b1));
            asm("mov.b64 %0,{%1,%1};" : "=l"(Bd[2]) : "f"(b2));
            asm("mov.b64 %0,{%1,%1};" : "=l"(Bd[3]) : "f"(b3));
            asm("mov.b64 %0,{%1,%1};" : "=l"(Bd[4]) : "f"(b4));
            asm("mov.b64 %0,{%1,%1};" : "=l"(Bd[5]) : "f"(b5));
            asm("mov.b64 %0,{%1,%1};" : "=l"(Bd[6]) : "f"(b6));
            asm("mov.b64 %0,{%1,%1};" : "=l"(Bd[7]) : "f"(b7));
#pragma unroll
            for (int j = 0; j < 8; j++) {
                FMA2(acc[0 * 8 + j], A0, Bd[j]);
                FMA2(acc[1 * 8 + j], A1, Bd[j]);
                FMA2(acc[2 * 8 + j], A2, Bd[j]);
                FMA2(acc[3 * 8 + j], A3, Bd[j]);
            }
        }

        // two 32-col chunks; threads with chunkq==q stage their 8 cols
#pragma unroll
        for (int q = 0; q < 2; q++) {
            if (chunkq == q) {
#pragma unroll
                for (int j = 0; j < 8; j++) {
                    float lo0, hi0, lo1, hi1, lo2, hi2, lo3, hi3;
                    asm("mov.b64 {%0,%1},%2;" : "=f"(lo0), "=f"(hi0) : "l"(acc[0 * 8 + j]));
                    asm("mov.b64 {%0,%1},%2;" : "=f"(lo1), "=f"(hi1) : "l"(acc[1 * 8 + j]));
                    asm("mov.b64 {%0,%1},%2;" : "=f"(lo2), "=f"(hi2) : "l"(acc[2 * 8 + j]));
                    asm("mov.b64 {%0,%1},%2;" : "=f"(lo3), "=f"(hi3) : "l"(acc[3 * 8 + j]));
                    float xc;
                    if (j == 0) xc = xq0.x; else if (j == 1) xc = xq0.y;
                    else if (j == 2) xc = xq0.z; else if (j == 3) xc = xq0.w;
                    else if (j == 4) xc = xq1.x; else if (j == 5) xc = xq1.y;
                    else if (j == 6) xc = xq1.z; else xc = xq1.w;
                    // EXACT score expression (matches reference noise):
                    float4 va = make_float4(2.f * lo0 - xra.x - xc, 2.f * hi0 - xra.y - xc,
                                            2.f * lo1 - xra.z - xc, 2.f * hi1 - xra.w - xc);
                    float4 vb = make_float4(2.f * lo2 - xrb.x - xc, 2.f * hi2 - xrb.y - xc,
                                            2.f * lo3 - xrb.z - xc, 2.f * hi3 - xrb.w - xc);
                    *(float4*)(Ss + (clcBase + j) * 128 + ra) = va;   // conflict-free
                    *(float4*)(Ss + (clcBase + j) * 128 + rb) = vb;
                }
            }
            __syncthreads();

            // scan: each thread scans its row over the 32 staged cols,
            // ascending column order (preserves lower-index-on-tie semantics)
            {
                const int cbase = col0 + q * 32;
#pragma unroll 4
                for (int j = 0; j < 32; j++) {
                    float s = Ss[j * 128 + tid];
                    if (s > sc[KK - 1]) {
                        int idv = cbase + j;
#pragma unroll
                        for (int p = KK - 1; p >= 1; --p) {
                            bool up  = s > sc[p - 1];
                            float ns = up ? sc[p - 1] : ((s > sc[p]) ? s   : sc[p]);
                            int   ni = up ? ix[p - 1] : ((s > sc[p]) ? idv : ix[p]);
                            sc[p] = ns; ix[p] = ni;
                        }
                        if (s > sc[0]) { sc[0] = s; ix[0] = idv; }
                    }
                }
            }
            __syncthreads();
        }
    }

    {
        size_t base = ((size_t)b * NN + row0 + tid) * KK;
#pragma unroll
        for (int p = 0; p < KK; p++) g_idx[base + p] = ix[p];
    }
}

// ---------------- fp64 exact rescoring of the 8 selected -> true order ----------------
__global__ void refine_kernel() {
    int b    = blockIdx.y;
    int n    = blockIdx.x * 8 + (threadIdx.x >> 5);
    int lane = threadIdx.x & 31;

    const float* ct = g_PT + ((size_t)b * NN + n) * CC;
    float cn[4];
#pragma unroll
    for (int i = 0; i < 4; i++) cn[i] = ct[lane + 32 * i];

    int* ip = g_idx + ((size_t)b * NN + n) * KK;
    double d[KK]; int id[KK];
#pragma unroll
    for (int k = 0; k < KK; k++) {
        int j = ip[k]; id[k] = j;
        const float* nt = g_PT + ((size_t)b * NN + j) * CC;
        double s = 0.0;
#pragma unroll
        for (int i = 0; i < 4; i++) {
            double df = (double)cn[i] - (double)nt[lane + 32 * i];
            s += df * df;
        }
#pragma unroll
        for (int o = 16; o > 0; o >>= 1) s += __shfl_xor_sync(0xffffffffu, s, o);
        d[k] = s;
    }

    if (lane == 0) {
        // insertion sort ascending by (d, idx): matches jax top_k ordering
        for (int a = 1; a < KK; a++) {
            double dv = d[a]; int iv = id[a]; int p = a - 1;
            while (p >= 0 && (d[p] > dv || (d[p] == dv && id[p] > iv))) {
                d[p + 1] = d[p]; id[p + 1] = id[p]; p--;
            }
            d[p + 1] = dv; id[p + 1] = iv;
        }
#pragma unroll
        for (int k = 0; k < KK; k++) ip[k] = id[k];
    }
}

// ---------------- G = conv2_w @ lrelu(points)  (per batch 128x4096x128) ----------------
__global__ void __launch_bounds__(256, 1) ggemm_kernel(const float* __restrict__ pts) {
    float* Ws = smem;              // [c][o] 128x128
    float* Fs = Ws + CC * CC;      // [c][n] 128x128
    const int tid = threadIdx.x;
    const int b = blockIdx.y;
    const int n0 = blockIdx.x * 128;
    const float* P = pts + (size_t)b * CC * NN;

    for (int i = tid; i < CC * CC / 4; i += 256)
        *(float4*)(Ws + i * 4) = *(const float4*)(g_WT + i * 4);
    for (int i = tid; i < CC * 128 / 4; i += 256) {
        int c = i >> 5; int n4 = (i & 31) << 2;
        float4 v = *(const float4*)(P + (size_t)c * NN + n0 + n4);
        v.x = lrelu(v.x); v.y = lrelu(v.y); v.z = lrelu(v.z); v.w = lrelu(v.w);
        *(float4*)(Fs + c * 128 + n4) = v;
    }
    __syncthreads();

    const int o0 = (tid & 15) * 8;
    const int m0 = (tid >> 4) * 8;
    float acc[8][8];
#pragma unroll
    for (int i = 0; i < 8; i++)
#pragma unroll
        for (int j = 0; j < 8; j++) acc[i][j] = 0.f;

#pragma unroll 2
    for (int k = 0; k < CC; k++) {
        float4 a0 = *(float4*)(Ws + k * CC + o0);
        float4 a1 = *(float4*)(Ws + k * CC + o0 + 4);
        float4 f0 = *(float4*)(Fs + k * 128 + m0);
        float4 f1 = *(float4*)(Fs + k * 128 + m0 + 4);
        float a[8] = { a0.x, a0.y, a0.z, a0.w, a1.x, a1.y, a1.z, a1.w };
        float f[8] = { f0.x, f0.y, f0.z, f0.w, f1.x, f1.y, f1.z, f1.w };
#pragma unroll
        for (int i = 0; i < 8; i++)
#pragma unroll
            for (int j = 0; j < 8; j++) acc[i][j] = fmaf(a[i], f[j], acc[i][j]);
    }

    float* Gp = g_G + (size_t)b * CC * NN;
#pragma unroll
    for (int i = 0; i < 8; i++) {
        float4 v0 = make_float4(acc[i][0], acc[i][1], acc[i][2], acc[i][3]);
        float4 v1 = make_float4(acc[i][4], acc[i][5], acc[i][6], acc[i][7]);
        *(float4*)(Gp + (size_t)(o0 + i) * NN + n0 + m0)     = v0;
        *(float4*)(Gp + (size_t)(o0 + i) * NN + n0 + m0 + 4) = v1;
    }
}

// ---------------- fused: out[b,c,n] and gnn[b,c,n,k] ----------------
// out = points + (lrelu(center) + sum_k lrelu(nbr))/9 ;  gnn = G[b,c,idx[b,n,k]]
__global__ void outgnn_kernel(const float* __restrict__ pts,
                              float* __restrict__ out, float* __restrict__ gnn) {
    __shared__ float prow[NN];
    __shared__ float grow[NN];
    int b = blockIdx.y, c = blockIdx.x;
    const float* P  = pts + ((size_t)b * CC + c) * NN;
    const float* Gp = g_G + ((size_t)b * CC + c) * NN;
    for (int i = threadIdx.x; i < NN / 4; i += 256) {
        *(float4*)(prow + i * 4) = *(const float4*)(P + i * 4);
        *(float4*)(grow + i * 4) = *(const float4*)(Gp + i * 4);
    }
    __syncthreads();
    float* gdst = gnn + ((size_t)b * CC + c) * NN * KK;
    for (int n = threadIdx.x; n < NN; n += 256) {
        const int4* ip = (const int4*)(g_idx + ((size_t)b * NN + n) * 8);
        int4 i0 = ip[0], i1 = ip[1];
        float x = prow[n];
        float s = lrelu(x);
        s += lrelu(prow[i0.x]); s += lrelu(prow[i0.y]); s += lrelu(prow[i0.z]); s += lrelu(prow[i0.w]);
        s += lrelu(prow[i1.x]); s += lrelu(prow[i1.y]); s += lrelu(prow[i1.z]); s += lrelu(prow[i1.w]);
        out[((size_t)b * CC + c) * NN + n] = x + s * (1.f / 9.f);
        float4 g0 = make_float4(grow[i0.x], grow[i0.y], grow[i0.z], grow[i0.w]);
        float4 g1 = make_float4(grow[i1.x], grow[i1.y], grow[i1.z], grow[i1.w]);
        *(float4*)(gdst + (size_t)n * KK)     = g0;
        *(float4*)(gdst + (size_t)n * KK + 4) = g1;
    }
}

// ---------------- launch ----------------
extern "C" void kernel_launch(void* const* d_in, const int* in_sizes, int n_in,
                              void* d_out, int out_size) {
    (void)in_sizes; (void)n_in; (void)out_size;
    const float* pts    = (const float*)d_in[0];
    // d_in[1] (W) is provably unused: mean(softmax) == 1/9 exactly.
    const float* conv2w = (const float*)d_in[2];
    float* out = (float*)d_out;
    float* gnn = out + (size_t)BB * CC * NN;

    cudaFuncSetAttribute(gram_topk_kernel, cudaFuncAttributeMaxDynamicSharedMemorySize, SMEM_FLOATS * 4);
    cudaFuncSetAttribute(ggemm_kernel,     cudaFuncAttributeMaxDynamicSharedMemorySize, 131072);

    xx_kernel<<<BB * NN / 256, 256>>>(pts);
    wt_kernel<<<CC * CC / 256, 256>>>(conv2w);
    pt_kernel<<<dim3(NN / 32, CC / 32, BB), dim3(32, 8)>>>(pts);
    gram_topk_kernel<<<dim3(NN / TM, BB), 128, SMEM_FLOATS * 4>>>(pts);
    refine_kernel<<<dim3(NN / 8, BB), 256>>>();
    ggemm_kernel<<<dim3(NN / 128, BB), 256, 131072>>>(pts);
    outgnn_kernel<<<dim3(CC, BB), 256>>>(pts, out, gnn);
}

// round 13
// speedup vs baseline: 1.0043x; 1.0043x over previous
#include <cuda_runtime.h>
#include <cstdint>

#define BB 8
#define CC 128
#define NN 4096
#define KK 8
#define TM 128
#define TN 64

// ---- device scratch (no allocations allowed) ----
__device__ float g_xx[BB * NN];
__device__ int   g_idx[BB * NN * KK];
__device__ float g_G[(size_t)BB * CC * NN];
__device__ float g_WT[CC * CC];
__device__ float g_PT[(size_t)BB * NN * CC];   // points transposed: [b][n][c]

__device__ __forceinline__ float lrelu(float x) { return x > 0.f ? x : 0.01f * x; }

extern __shared__ __align__(16) float smem[];

// ---------------- xx[b,n] = sum_c points^2 ----------------
__global__ void xx_kernel(const float* __restrict__ pts) {
    int t = blockIdx.x * blockDim.x + threadIdx.x;   // b*N + n
    int b = t >> 12, n = t & (NN - 1);
    const float* p = pts + (size_t)b * CC * NN + n;
    float s = 0.f;
#pragma unroll
    for (int c = 0; c < CC; c++) { float v = p[(size_t)c * NN]; s = fmaf(v, v, s); }
    g_xx[t] = s;
}

// ---------------- transpose conv2_w -> g_WT[c][o] ----------------
__global__ void wt_kernel(const float* __restrict__ w) {
    int t = blockIdx.x * blockDim.x + threadIdx.x;   // o*128 + c
    int o = t >> 7, c = t & 127;
    g_WT[c * CC + o] = w[t];
}

// ---------------- transpose points -> g_PT[b][n][c] ----------------
__global__ void pt_kernel(const float* __restrict__ pts) {
    __shared__ float t[32][33];
    int b  = blockIdx.z;
    int c0 = blockIdx.y * 32, n0 = blockIdx.x * 32;
    for (int i = threadIdx.y; i < 32; i += 8)
        t[i][threadIdx.x] = pts[(size_t)b * CC * NN + (size_t)(c0 + i) * NN + n0 + threadIdx.x];
    __syncthreads();
    for (int i = threadIdx.y; i < 32; i += 8)
        g_PT[((size_t)b * NN + n0 + i) * CC + c0 + threadIdx.x] = t[threadIdx.x][i];
}

// ---------------- fused Gram + top-8 (the hot kernel) ----------------
// 128 threads/CTA, 2 CTAs/SM. Thread = 8 rows (rg*4+{0..3} and 64+rg*4+{0..3})
// x 8 cols (cg*8..cg*8+7). A loaded as 2 conflict-free ld.shared.v2.b64 giving
// NATURAL row-pairs for FFMA2 (no A packs); B via 2 broadcast ld.shared.v4.b32
// + 8 dup packs. Per-(row,col) accumulation chain over k and the score
// expression 2*inner - xr - xc are bit-identical to the verified round-6
// kernel, so fp32 selection decisions match the reference's top_k everywhere.
#define FMA2(ACC, A, Bv) asm("fma.rn.f32x2 %0,%1,%2,%0;" : "+l"(ACC) : "l"(A), "l"(Bv))

#define SMEM_FLOATS (CC * TM + CC * TN + 32 * 128)   // 28672 floats = 112KB

__global__ void __launch_bounds__(128, 2) gram_topk_kernel(const float* __restrict__ pts) {
    float* As = smem;                 // [k][r] 128x128 = 64KB
    float* Bs = As + CC * TM;         // [k][c] 128x64  = 32KB
    float* Ss = Bs + CC * TN;         // [32][128] col-major chunk = 16KB

    const int tid  = threadIdx.x;
    const int rg   = tid & 15;        // row group
    const int cg   = tid >> 4;        // col group (0..7)
    const int ra   = rg * 4;          // rows ra..ra+3
    const int rb   = 64 + rg * 4;     // rows rb..rb+3
    const int c0   = cg * 8;          // cols c0..c0+7
    const int chunkq  = cg >> 2;      // which 32-col chunk this thread stages
    const int clcBase = (cg & 3) * 8; // col offset within chunk

    const int b    = blockIdx.y;
    const int row0 = blockIdx.x * TM;
    const float* P = pts + (size_t)b * CC * NN;

    // Load A tile once (coalesced, k-major, rows contiguous)
    for (int i = tid; i < CC * TM / 4; i += 128) {
        int k = i >> 5, r4 = (i & 31) << 2;
        *(float4*)(As + k * TM + r4) = *(const float4*)(P + (size_t)k * NN + row0 + r4);
    }

    // row norms for this thread's 8 rows
    float4 xra = *(const float4*)(g_xx + b * NN + row0 + ra);
    float4 xrb = *(const float4*)(g_xx + b * NN + row0 + rb);

    // per-thread sorted top-8 (thread owns row row0+tid for the scan)
    float sc[KK]; int ix[KK];
#pragma unroll
    for (int p = 0; p < KK; p++) { sc[p] = -3e38f; ix[p] = 0; }

    unsigned aAddr = (unsigned)__cvta_generic_to_shared(As) + rg * 16;
    unsigned bAddr = (unsigned)__cvta_generic_to_shared(Bs) + cg * 32;

    for (int ct = 0; ct < NN / TN; ct++) {
        const int col0 = ct * TN;

        for (int i = tid; i < CC * TN / 4; i += 128) {
            int k = i >> 4, c4 = (i & 15) << 2;
            *(float4*)(Bs + k * TN + c4) = *(const float4*)(P + (size_t)k * NN + col0 + c4);
        }
        __syncthreads();

        // col norms for this thread's 8 cols (hidden under compute)
        float4 xq0 = *(const float4*)(g_xx + b * NN + col0 + c0);
        float4 xq1 = *(const float4*)(g_xx + b * NN + col0 + c0 + 4);

        unsigned long long acc[32];   // acc[p*8+j]: row-pair p, col c0+j
#pragma unroll
        for (int i = 0; i < 32; i++) acc[i] = 0ULL;

#pragma unroll 4
        for (int k = 0; k < CC; k++) {
            unsigned long long A0, A1, A2, A3;
            asm volatile("ld.shared.v2.b64 {%0,%1},[%2];"
                         : "=l"(A0), "=l"(A1) : "r"(aAddr + k * (TM * 4)));
            asm volatile("ld.shared.v2.b64 {%0,%1},[%2];"
                         : "=l"(A2), "=l"(A3) : "r"(aAddr + k * (TM * 4) + 256));
            float b0, b1, b2, b3, b4, b5, b6, b7;
            asm volatile("ld.shared.v4.b32 {%0,%1,%2,%3},[%4];"
                         : "=f"(b0), "=f"(b1), "=f"(b2), "=f"(b3)
                         : "r"(bAddr + k * (TN * 4)));
            asm volatile("ld.shared.v4.b32 {%0,%1,%2,%3},[%4];"
                         : "=f"(b4), "=f"(b5), "=f"(b6), "=f"(b7)
                         : "r"(bAddr + k * (TN * 4) + 16));
            unsigned long long Bd[8];
            asm("mov.b64 %0,{%1,%1};" : "=l"(Bd[0]) : "f"(b0));
            asm("mov.b64 %0,{%1,%1};" : "=l"(Bd[1]) : "f"(b1));
            asm("mov.b64 %0,{%1,%1};" : "=l"(Bd[2]) : "f"(b2));
            asm("mov.b64 %0,{%1,%1};" : "=l"(Bd[3]) : "f"(b3));
            asm("mov.b64 %0,{%1,%1};" : "=l"(Bd[4]) : "f"(b4));
            asm("mov.b64 %0,{%1,%1};" : "=l"(Bd[5]) : "f"(b5));
            asm("mov.b64 %0,{%1,%1};" : "=l"(Bd[6]) : "f"(b6));
            asm("mov.b64 %0,{%1,%1};" : "=l"(Bd[7]) : "f"(b7));
#pragma unroll
            for (int j = 0; j < 8; j++) {
                FMA2(acc[0 * 8 + j], A0, Bd[j]);
                FMA2(acc[1 * 8 + j], A1, Bd[j]);
                FMA2(acc[2 * 8 + j], A2, Bd[j]);
                FMA2(acc[3 * 8 + j], A3, Bd[j]);
            }
        }

        // two 32-col chunks; threads with chunkq==q stage their 8 cols
#pragma unroll
        for (int q = 0; q < 2; q++) {
            if (chunkq == q) {
#pragma unroll
                for (int j = 0; j < 8; j++) {
                    float lo0, hi0, lo1, hi1, lo2, hi2, lo3, hi3;
                    asm("mov.b64 {%0,%1},%2;" : "=f"(lo0), "=f"(hi0) : "l"(acc[0 * 8 + j]));
                    asm("mov.b64 {%0,%1},%2;" : "=f"(lo1), "=f"(hi1) : "l"(acc[1 * 8 + j]));
                    asm("mov.b64 {%0,%1},%2;" : "=f"(lo2), "=f"(hi2) : "l"(acc[2 * 8 + j]));
                    asm("mov.b64 {%0,%1},%2;" : "=f"(lo3), "=f"(hi3) : "l"(acc[3 * 8 + j]));
                    float xc;
                    if (j == 0) xc = xq0.x; else if (j == 1) xc = xq0.y;
                    else if (j == 2) xc = xq0.z; else if (j == 3) xc = xq0.w;
                    else if (j == 4) xc = xq1.x; else if (j == 5) xc = xq1.y;
                    else if (j == 6) xc = xq1.z; else xc = xq1.w;
                    // EXACT score expression (matches reference noise):
                    float4 va = make_float4(2.f * lo0 - xra.x - xc, 2.f * hi0 - xra.y - xc,
                                            2.f * lo1 - xra.z - xc, 2.f * hi1 - xra.w - xc);
                    float4 vb = make_float4(2.f * lo2 - xrb.x - xc, 2.f * hi2 - xrb.y - xc,
                                            2.f * lo3 - xrb.z - xc, 2.f * hi3 - xrb.w - xc);
                    *(float4*)(Ss + (clcBase + j) * 128 + ra) = va;   // conflict-free
                    *(float4*)(Ss + (clcBase + j) * 128 + rb) = vb;
                }
            }
            __syncthreads();

            // scan: each thread scans its row over the 32 staged cols,
            // ascending column order (preserves lower-index-on-tie semantics)
            {
                const int cbase = col0 + q * 32;
#pragma unroll 4
                for (int j = 0; j < 32; j++) {
                    float s = Ss[j * 128 + tid];
                    if (s > sc[KK - 1]) {
                        int idv = cbase + j;
#pragma unroll
                        for (int p = KK - 1; p >= 1; --p) {
                            bool up  = s > sc[p - 1];
                            float ns = up ? sc[p - 1] : ((s > sc[p]) ? s   : sc[p]);
                            int   ni = up ? ix[p - 1] : ((s > sc[p]) ? idv : ix[p]);
                            sc[p] = ns; ix[p] = ni;
                        }
                        if (s > sc[0]) { sc[0] = s; ix[0] = idv; }
                    }
                }
            }
            __syncthreads();
        }
    }

    {
        size_t base = ((size_t)b * NN + row0 + tid) * KK;
#pragma unroll
        for (int p = 0; p < KK; p++) g_idx[base + p] = ix[p];
    }
}

// ---------------- fp64 exact rescoring of the 8 selected -> true order ----------------
__global__ void refine_kernel() {
    int b    = blockIdx.y;
    int n    = blockIdx.x * 8 + (threadIdx.x >> 5);
    int lane = threadIdx.x & 31;

    const float* ct = g_PT + ((size_t)b * NN + n) * CC;
    float cn[4];
#pragma unroll
    for (int i = 0; i < 4; i++) cn[i] = ct[lane + 32 * i];

    int* ip = g_idx + ((size_t)b * NN + n) * KK;
    double d[KK]; int id[KK];
#pragma unroll
    for (int k = 0; k < KK; k++) {
        int j = ip[k]; id[k] = j;
        const float* nt = g_PT + ((size_t)b * NN + j) * CC;
        double s = 0.0;
#pragma unroll
        for (int i = 0; i < 4; i++) {
            double df = (double)cn[i] - (double)nt[lane + 32 * i];
            s += df * df;
        }
#pragma unroll
        for (int o = 16; o > 0; o >>= 1) s += __shfl_xor_sync(0xffffffffu, s, o);
        d[k] = s;
    }

    if (lane == 0) {
        // insertion sort ascending by (d, idx): matches jax top_k ordering
        for (int a = 1; a < KK; a++) {
            double dv = d[a]; int iv = id[a]; int p = a - 1;
            while (p >= 0 && (d[p] > dv || (d[p] == dv && id[p] > iv))) {
                d[p + 1] = d[p]; id[p + 1] = id[p]; p--;
            }
            d[p + 1] = dv; id[p + 1] = iv;
        }
#pragma unroll
        for (int k = 0; k < KK; k++) ip[k] = id[k];
    }
}

// ---------------- G = conv2_w @ lrelu(points)  (per batch 128x4096x128) ----------------
__global__ void __launch_bounds__(256, 1) ggemm_kernel(const float* __restrict__ pts) {
    float* Ws = smem;              // [c][o] 128x128
    float* Fs = Ws + CC * CC;      // [c][n] 128x128
    const int tid = threadIdx.x;
    const int b = blockIdx.y;
    const int n0 = blockIdx.x * 128;
    const float* P = pts + (size_t)b * CC * NN;

    for (int i = tid; i < CC * CC / 4; i += 256)
        *(float4*)(Ws + i * 4) = *(const float4*)(g_WT + i * 4);
    for (int i = tid; i < CC * 128 / 4; i += 256) {
        int c = i >> 5; int n4 = (i & 31) << 2;
        float4 v = *(const float4*)(P + (size_t)c * NN + n0 + n4);
        v.x = lrelu(v.x); v.y = lrelu(v.y); v.z = lrelu(v.z); v.w = lrelu(v.w);
        *(float4*)(Fs + c * 128 + n4) = v;
    }
    __syncthreads();

    const int o0 = (tid & 15) * 8;
    const int m0 = (tid >> 4) * 8;
    float acc[8][8];
#pragma unroll
    for (int i = 0; i < 8; i++)
#pragma unroll
        for (int j = 0; j < 8; j++) acc[i][j] = 0.f;

#pragma unroll 2
    for (int k = 0; k < CC; k++) {
        float4 a0 = *(float4*)(Ws + k * CC + o0);
        float4 a1 = *(float4*)(Ws + k * CC + o0 + 4);
        float4 f0 = *(float4*)(Fs + k * 128 + m0);
        float4 f1 = *(float4*)(Fs + k * 128 + m0 + 4);
        float a[8] = { a0.x, a0.y, a0.z, a0.w, a1.x, a1.y, a1.z, a1.w };
        float f[8] = { f0.x, f0.y, f0.z, f0.w, f1.x, f1.y, f1.z, f1.w };
#pragma unroll
        for (int i = 0; i < 8; i++)
#pragma unroll
            for (int j = 0; j < 8; j++) acc[i][j] = fmaf(a[i], f[j], acc[i][j]);
    }

    float* Gp = g_G + (size_t)b * CC * NN;
#pragma unroll
    for (int i = 0; i < 8; i++) {
        float4 v0 = make_float4(acc[i][0], acc[i][1], acc[i][2], acc[i][3]);
        float4 v1 = make_float4(acc[i][4], acc[i][5], acc[i][6], acc[i][7]);
        *(float4*)(Gp + (size_t)(o0 + i) * NN + n0 + m0)     = v0;
        *(float4*)(Gp + (size_t)(o0 + i) * NN + n0 + m0 + 4) = v1;
    }
}

// ---------------- fused: out[b,c,n] and gnn[b,c,n,k] ----------------
// out = points + (lrelu(center) + sum_k lrelu(nbr))/9 ;  gnn = G[b,c,idx[b,n,k]]
__global__ void outgnn_kernel(const float* __restrict__ pts,
                              float* __restrict__ out, float* __restrict__ gnn) {
    __shared__ float prow[NN];
    __shared__ float grow[NN];
    int b = blockIdx.y, c = blockIdx.x;
    const float* P  = pts + ((size_t)b * CC + c) * NN;
    const float* Gp = g_G + ((size_t)b * CC + c) * NN;
    for (int i = threadIdx.x; i < NN / 4; i += 256) {
        *(float4*)(prow + i * 4) = *(const float4*)(P + i * 4);
        *(float4*)(grow + i * 4) = *(const float4*)(Gp + i * 4);
    }
    __syncthreads();
    float* gdst = gnn + ((size_t)b * CC + c) * NN * KK;
    for (int n = threadIdx.x; n < NN; n += 256) {
        const int4* ip = (const int4*)(g_idx + ((size_t)b * NN + n) * 8);
        int4 i0 = ip[0], i1 = ip[1];
        float x = prow[n];
        float s = lrelu(x);
        s += lrelu(prow[i0.x]); s += lrelu(prow[i0.y]); s += lrelu(prow[i0.z]); s += lrelu(prow[i0.w]);
        s += lrelu(prow[i1.x]); s += lrelu(prow[i1.y]); s += lrelu(prow[i1.z]); s += lrelu(prow[i1.w]);
        out[((size_t)b * CC + c) * NN + n] = x + s * (1.f / 9.f);
        float4 g0 = make_float4(grow[i0.x], grow[i0.y], grow[i0.z], grow[i0.w]);
        float4 g1 = make_float4(grow[i1.x], grow[i1.y], grow[i1.z], grow[i1.w]);
        *(float4*)(gdst + (size_t)n * KK)     = g0;
        *(float4*)(gdst + (size_t)n * KK + 4) = g1;
    }
}

// ---------------- launch ----------------
extern "C" void kernel_launch(void* const* d_in, const int* in_sizes, int n_in,
                              void* d_out, int out_size) {
    (void)in_sizes; (void)n_in; (void)out_size;
    const float* pts    = (const float*)d_in[0];
    // d_in[1] (W) is provably unused: mean(softmax) == 1/9 exactly.
    const float* conv2w = (const float*)d_in[2];
    float* out = (float*)d_out;
    float* gnn = out + (size_t)BB * CC * NN;

    cudaFuncSetAttribute(gram_topk_kernel, cudaFuncAttributeMaxDynamicSharedMemorySize, SMEM_FLOATS * 4);
    cudaFuncSetAttribute(ggemm_kernel,     cudaFuncAttributeMaxDynamicSharedMemorySize, 131072);

    xx_kernel<<<BB * NN / 256, 256>>>(pts);
    wt_kernel<<<CC * CC / 256, 256>>>(conv2w);
    pt_kernel<<<dim3(NN / 32, CC / 32, BB), dim3(32, 8)>>>(pts);
    gram_topk_kernel<<<dim3(NN / TM, BB), 128, SMEM_FLOATS * 4>>>(pts);
    refine_kernel<<<dim3(NN / 8, BB), 256>>>();
    ggemm_kernel<<<dim3(NN / 128, BB), 256, 131072>>>(pts);
    outgnn_kernel<<<dim3(CC, BB), 256>>>(pts, out, gnn);
}